// round 14
// baseline (speedup 1.0000x reference)
#include <cuda_runtime.h>
#include <cstdint>

// Problem constants (match reference)
#define BN 64
#define TN 1024
#define DN 256
#define KMAX 128
#define EPSF 1e-3f
#define MMAXT 64                        // table depth (max cluster size covered)
#define HALF_L2PI 0.91893853320467274f  // 0.5*log(2*pi)
#define LN2F 0.69314718055994531f
#define LOG2EF 1.44269504088896340f
// C1 = ln(log2e) - 0.5*ln(pi)  (per-nonzero-obs scale residue)
#define C1F (-0.20585202294f)

// ---------------------------------------------------------------------------
// Static device scratch
// ---------------------------------------------------------------------------
__device__ int   g_cnt [BN * KMAX];
__device__ int   g_list[BN * KMAX * TN];   // PRE-SCALED float4-row offsets, padded +4

// per-dim packed loop constants: {kappa0, a, kl2, cb}
__device__ float4 g_c4[DN];
// fallback-path constants
__device__ float g_a0[DN], g_b0[DN];
__device__ float g_lgA0B0[DN], g_lgA0[DN], g_lgB0[DN], g_lgA[DN], g_lgK[DN];

// tables indexed by count m (telescoped chain-end sums)
// g_tabNZ[m][d] = [lg(a0+m)-lg(a0)] + [lg(a+m/2)-lg(a)] + [lg(k0+m)-lg(k0)]
//               + LN2 * tc(m)   (telescoped Student-t constant, closed form)
__device__ float g_tabNZ[MMAXT * DN];
__device__ float g_tabB0[MMAXT * DN];   // lg(b0+m)-lg(b0)
__device__ float g_tabAB[MMAXT * DN];   // lg(a0+b0+m)-lg(a0+b0)

// ---------------------------------------------------------------------------
// Fast lgamma for x > 0: shift to x>=8 (unrolled, predicated), then Stirling.
// ---------------------------------------------------------------------------
__device__ __forceinline__ float fast_lgamma(float x)
{
    float prod = 1.0f;
#pragma unroll
    for (int i = 0; i < 8; i++) {
        if (x < 8.0f) { prod *= x; x += 1.0f; }
    }
    float rx  = __frcp_rn(x);
    float rx2 = rx * rx;
    float ser = rx * (8.33333333e-2f + rx2 * (-2.77777778e-3f + rx2 * 7.93650794e-4f));
    float lx  = __logf(x);
    return fmaf(x - 0.5f, lx, -x) + HALF_L2PI + ser - __logf(prod);
}

// ---------------------------------------------------------------------------
// Kernel 1 (fused prep): blocks [0, MMAXT) build tables + constants;
// blocks [MMAXT, MMAXT+8) build per-(b,k) time lists (one warp per batch row).
// ---------------------------------------------------------------------------
__global__ void __launch_bounds__(256)
k_prep(const float* __restrict__ loc,
       const float* __restrict__ log_mean_conc,
       const float* __restrict__ log_conc,
       const float* __restrict__ log_scale,
       const float* __restrict__ sparse_prior_logit,
       const int*   __restrict__ z,
       float* __restrict__ out)
{
    if (blockIdx.x < MMAXT) {
        const int m = blockIdx.x;
        const int d = threadIdx.x;
        float kappa0 = expf(fminf(log_mean_conc[d], 12.0f));
        float a      = expf(log_conc[d]);
        float b      = expf(log_scale[d]);
        float a0     = 2.0f * a + 4.0f;                 // nu+1, nu = 2a+3
        float b0     = a0 * expf(sparse_prior_logit[d]);
        float l      = loc[d];
        float kl2    = LOG2EF * kappa0 * l;
        float cb     = (LOG2EF * LOG2EF) * fmaf(kappa0 * l, l, 2.0f * b);

        float lgA0 = fast_lgamma(a0);
        float lgB0 = fast_lgamma(b0);
        float lgAB = fast_lgamma(a0 + b0);
        float lgA  = fast_lgamma(a);
        float lgK  = fast_lgamma(kappa0);

        if (m == 0) {
            g_c4[d] = make_float4(kappa0, a, kl2, cb);
            g_a0[d]     = a0;
            g_b0[d]     = b0;
            // exact bases for the (rare) cnt>=MMAXT fallback path
            g_lgA0[d]   = lgammaf(a0);
            g_lgB0[d]   = lgammaf(b0);
            g_lgA0B0[d] = lgammaf(a0 + b0);
            g_lgA[d]    = lgammaf(a);
            g_lgK[d]    = lgammaf(kappa0);
            if (d < BN) out[d] = 0.0f;                  // out is poisoned
        }

        float fm = (float)m;
        // telescoped Student-t constant, CLOSED FORM (Abel summation):
        // S(m) = Sum_{i=0}^{m-2} (a+(i+1)/2)[L(i+2)-L(i)], L(j)=log2(k0+j)
        //      = -Sum_{j=2}^{m-2} L(j)
        //        + (a+(m-2)/2)L(m-1) + (a+(m-1)/2)L(m)
        //        - (a+1/2)L(0) - (a+1)L(1)              (m >= 3)
        // with Sum_{j=2}^{m-2} L(j) = log2[G(k0+m-1)/G(k0+2)].
        float tc = 0.0f;
        if (m >= 1) {
            float t10 = fmaf(cb, kappa0, -kl2 * kl2);   // t1 at M=0 (scaled)
            float p0  = t10 * (kappa0 + 1.0f);
            tc = a * __log2f(p0);
            if (m == 2) {
                tc += (a + 0.5f) * (__log2f(kappa0 + 2.0f) - __log2f(kappa0));
            } else if (m >= 3) {
                float mid = LOG2EF * (fast_lgamma(kappa0 + fm - 1.0f)
                                    - fast_lgamma(kappa0 + 2.0f));
                tc += -mid
                    + fmaf(0.5f, fm - 2.0f, a) * __log2f(kappa0 + fm - 1.0f)
                    + fmaf(0.5f, fm - 1.0f, a) * __log2f(kappa0 + fm)
                    - (a + 0.5f) * __log2f(kappa0)            // c_0 = a+1/2
                    - (a + 1.0f) * __log2f(kappa0 + 1.0f);    // c_1 = a+1
            }
        }
        g_tabNZ[m * DN + d] = (fast_lgamma(a0 + fm)           - lgA0)
                            + (fast_lgamma(fmaf(0.5f, fm, a)) - lgA)
                            + (fast_lgamma(kappa0 + fm)       - lgK)
                            + LN2F * tc;
        g_tabB0[m * DN + d] = fast_lgamma(b0 + fm)            - lgB0;
        g_tabAB[m * DN + d] = fast_lgamma(a0 + b0 + fm)       - lgAB;
    } else {
        // ---- list build: one warp per batch row ----
        __shared__ int cs[8][KMAX];
        const int wl   = threadIdx.x >> 5;
        const int lane = threadIdx.x & 31;
        const int b    = (blockIdx.x - MMAXT) * 8 + wl;

        for (int i = threadIdx.x; i < 8 * KMAX; i += blockDim.x)
            ((int*)cs)[i] = 0;
        __syncthreads();

        const int* zr = z + b * TN;
        int* cw = cs[wl];
        const unsigned lmlt = (1u << lane) - 1u;

        for (int t0 = 0; t0 < TN; t0 += 32) {
            int t  = t0 + lane;
            int zv = __ldg(zr + t);                          // coalesced
            unsigned mask = __match_any_sync(0xffffffffu, zv);
            int rank = __popc(mask & lmlt);                  // stable in-chunk rank
            int base = cw[zv];
            __syncwarp();
            g_list[((size_t)(b * KMAX + zv)) * TN + base + rank] = t * (DN / 4);
            if (rank == 0)
                cw[zv] = base + __popc(mask);
            __syncwarp();
        }

        // counts + PAD each list with 4 duplicates of the last entry so the
        // main loop needs no index clamps (duplicates are masked at consume).
        for (int k = lane; k < KMAX; k += 32) {
            int c = cw[k];
            g_cnt[b * KMAX + k] = c;
            if (c > 0) {
                size_t base = ((size_t)(b * KMAX + k)) * TN;
                int last = g_list[base + c - 1];
#pragma unroll
                for (int i = 0; i < 4; i++) {
                    int idx = c + i;
                    if (idx > TN - 1) idx = TN - 1;
                    g_list[base + idx] = last;
                }
            }
        }
    }
}

// ---------------------------------------------------------------------------
// Sufficient-stat-only per-element update (the whole Student-t log sum is
// telescoped out of the loop). A padded/zero element is a no-op.
// ---------------------------------------------------------------------------
__device__ __forceinline__ void obs_lite(float x, float& w, float& s2p, float& m1)
{
    float nzf = (x > EPSF) ? 1.0f : 0.0f;
    float y   = __log2f(fmaxf(x, EPSF));
    float yn  = y * nzf;
    w   += yn;
    s2p  = fmaf(yn, y, s2p);
    m1  += nzf;
}

// ---------------------------------------------------------------------------
// Chain-end terms for one dim. Telescoped Student-t final term:
//   - (a + M/2) * ln Q_final, Q_final = (s2p*kn - w^2) * (kn - 1), kn = k0 + M
// plus table-telescoped hurdle/CRP-emission lgamma sums.
// ---------------------------------------------------------------------------
__device__ __forceinline__ float tail3(int d, int cnt, float m1, float w, float s2p,
                                       float kap, float a, float kl2)
{
    const int M1 = (int)m1;
    const int Z  = cnt - M1;
    float s1  = w - kl2;
    float kn  = kap + m1;
    float t1f = fmaf(s2p, kn, -w * w);
    float qf  = t1f * (kn - 1.0f);
    float lq  = __log2f(fmaxf(qf, 1e-37f));
    float cf  = (m1 > 0.5f) ? fmaf(0.5f, m1, a) : 0.0f;   // gate M=0 (qf may be <=0)
    float r = fmaf(C1F, m1, -LN2F * s1);     // -0.5*ln(pi) residue, -Sum y
    r -= LN2F * cf * lq;                     // -(a+M/2)*ln(Q_final)
    if (cnt < MMAXT) {
        r += g_tabNZ[M1 * DN + d]      // nonzero-obs lgammas + telescoped t const
           + g_tabB0[Z  * DN + d]      // Sum log(b0+n0)       (zero obs)
           - g_tabAB[cnt * DN + d];    // -Sum log(a0+b0+ck)
    } else {
        // rare fallback: direct evaluation (exact small loop)
        float a0 = g_a0[d], b0 = g_b0[d];
        float tc = 0.0f;
        if (M1 >= 1) {
            float t10 = fmaf(((const float4*)g_c4)[d].w, kap, -kl2 * kl2);
            float p0  = t10 * (kap + 1.0f);
            tc = a * __log2f(p0);
            for (int i = 0; i + 2 <= M1; i++) {
                float ratio = __fdividef(kap + (float)(i + 2), kap + (float)i);
                tc = fmaf(fmaf(0.5f, (float)(i + 1), a), __log2f(ratio), tc);
            }
        }
        r += LN2F * tc
           + (lgammaf(a0 + m1)              - g_lgA0[d])
           + (lgammaf(b0 + (float)Z)        - g_lgB0[d])
           + (lgammaf(fmaf(0.5f, m1, a))    - g_lgA[d])
           + (lgammaf(kap + m1)             - g_lgK[d])
           - (lgammaf(a0 + b0 + (float)cnt) - g_lgA0B0[d]);
    }
    return r;
}

// ---------------------------------------------------------------------------
// Kernel 2: main chain evaluation.
// One CTA per (b,k) chain, 64 threads; thread t owns dims 4t..4t+3. The CTA
// streams its cluster's X rows as coalesced float4, 2 time-steps per loop
// with depth-2 prefetch. Lists are padded, so no index clamps; padded slots
// are masked to x=0 (no-op through obs_lite).
// ---------------------------------------------------------------------------
__global__ void __launch_bounds__(64)
k_main(const float* __restrict__ X, float* __restrict__ out)
{
    const int id = blockIdx.x;            // chain id = b*KMAX + k
    const int b  = id >> 7;
    const int k  = id & (KMAX - 1);
    const int t  = threadIdx.x;           // dims 4t..4t+3

    const int cnt = g_cnt[id];
    float accN = 0.0f;

    if (cnt > 0) {
        const float4 C0 = __ldg(&g_c4[4 * t]);      // {kappa0, a, kl2, cb}
        const float4 C1 = __ldg(&g_c4[4 * t + 1]);
        const float4 C2 = __ldg(&g_c4[4 * t + 2]);
        const float4 C3 = __ldg(&g_c4[4 * t + 3]);

        const int* lst = g_list + (size_t)id * TN;
        const float4* Xb = (const float4*)X + ((size_t)b * TN) * (DN / 4) + t;

        float w0 = C0.z, p0 = C0.w, m0 = 0.f;
        float w1 = C1.z, p1 = C1.w, m1 = 0.f;
        float w2 = C2.z, p2 = C2.w, m2 = 0.f;
        float w3 = C3.z, p3 = C3.w, m3 = 0.f;

        // prime depth-2 pipeline (padded list: no clamps needed)
        int oa = __ldg(lst);
        int ob = __ldg(lst + 1);
        float4 x0 = __ldg(Xb + (size_t)oa);
        float4 x1 = __ldg(Xb + (size_t)ob);

        const int cnt2 = (cnt + 1) & ~1;           // round up to even
        for (int j = 0; j < cnt2; j += 2) {
            int on0 = __ldg(lst + j + 2);
            int on1 = __ldg(lst + j + 3);
            float4 xn0 = __ldg(Xb + (size_t)on0);
            float4 xn1 = __ldg(Xb + (size_t)on1);

            // slot 0 (always in range: j < cnt)
            obs_lite(x0.x, w0, p0, m0);
            obs_lite(x0.y, w1, p1, m1);
            obs_lite(x0.z, w2, p2, m2);
            obs_lite(x0.w, w3, p3, m3);

            // slot 1 (mask padded element to 0 -> no-op)
            float msk = (j + 1 < cnt) ? 1.0f : 0.0f;
            obs_lite(x1.x * msk, w0, p0, m0);
            obs_lite(x1.y * msk, w1, p1, m1);
            obs_lite(x1.z * msk, w2, p2, m2);
            obs_lite(x1.w * msk, w3, p3, m3);

            x0 = xn0;
            x1 = xn1;
        }

        const int d0 = 4 * t;
        accN  = tail3(d0,     cnt, m0, w0, p0, C0.x, C0.y, C0.z);
        accN += tail3(d0 + 1, cnt, m1, w1, p1, C1.x, C1.y, C1.z);
        accN += tail3(d0 + 2, cnt, m2, w2, p2, C2.x, C2.y, C2.z);
        accN += tail3(d0 + 3, cnt, m3, w3, p3, C3.x, C3.y, C3.z);
    }

    // CRP (fully telescoped): Sum_k lgamma(cnt_k) - lgamma(T+1) per batch row
    if (t == 0) {
        if (cnt > 0) accN += fast_lgamma((float)cnt);
        if (k == 0)  accN -= lgammaf((float)(TN + 1));
    }

    // 2-warp reduction
    const int lane = t & 31, wid = t >> 5;
#pragma unroll
    for (int o = 16; o; o >>= 1)
        accN += __shfl_down_sync(0xffffffffu, accN, o);
    __shared__ float wsum[2];
    if (lane == 0) wsum[wid] = accN;
    __syncthreads();
    if (t == 0)
        atomicAdd(&out[b], -(wsum[0] + wsum[1]));
}

// ---------------------------------------------------------------------------
// Entry point. Inputs: X, loc, log_mean_conc, log_conc, log_scale,
// sparse_prior_logit, z. Output: float[BN].
// ---------------------------------------------------------------------------
extern "C" void kernel_launch(void* const* d_in, const int* in_sizes, int n_in,
                              void* d_out, int out_size)
{
    const float* X   = (const float*)d_in[0];
    const float* loc = (const float*)d_in[1];
    const float* lmc = (const float*)d_in[2];
    const float* lc  = (const float*)d_in[3];
    const float* ls  = (const float*)d_in[4];
    const float* spl = (const float*)d_in[5];
    const int*   z   = (const int*)d_in[6];
    float* out = (float*)d_out;

    k_prep<<<MMAXT + BN / 8, 256>>>(loc, lmc, lc, ls, spl, z, out);
    k_main<<<BN * KMAX, 64>>>(X, out);
}

// round 15
// speedup vs baseline: 1.1227x; 1.1227x over previous
#include <cuda_runtime.h>
#include <cstdint>

// Problem constants (match reference)
#define BN 64
#define TN 1024
#define DN 256
#define KMAX 128
#define EPSF 1e-3f
#define MMAXT 64                        // table depth (max cluster size covered)
#define HALF_L2PI 0.91893853320467274f  // 0.5*log(2*pi)
#define LN2F 0.69314718055994531f
#define LOG2EF 1.44269504088896340f
// C1 = ln(log2e) - 0.5*ln(pi)  (per-nonzero-obs scale residue)
#define C1F (-0.20585202294f)

// ---------------------------------------------------------------------------
// Static device scratch
// ---------------------------------------------------------------------------
__device__ int   g_cnt [BN * KMAX];
__device__ int   g_list[BN * KMAX * TN];   // PRE-SCALED float4-row offsets, padded +4

// per-dim packed loop constants: {kappa0, a, kl2, cb}
__device__ float4 g_c4[DN];
// fallback-path constants
__device__ float g_a0[DN], g_b0[DN];
__device__ float g_lgA0B0[DN], g_lgA0[DN], g_lgB0[DN], g_lgA[DN], g_lgK[DN];

// tables indexed by count m (telescoped chain-end sums)
__device__ float g_tabNZ[MMAXT * DN];
__device__ float g_tabB0[MMAXT * DN];   // lg(b0+m)-lg(b0)
__device__ float g_tabAB[MMAXT * DN];   // lg(a0+b0+m)-lg(a0+b0)

// ---------------------------------------------------------------------------
// Fast lgamma for x > 0: shift to x>=8 (unrolled, predicated), then Stirling.
// ---------------------------------------------------------------------------
__device__ __forceinline__ float fast_lgamma(float x)
{
    float prod = 1.0f;
#pragma unroll
    for (int i = 0; i < 8; i++) {
        if (x < 8.0f) { prod *= x; x += 1.0f; }
    }
    float rx  = __frcp_rn(x);
    float rx2 = rx * rx;
    float ser = rx * (8.33333333e-2f + rx2 * (-2.77777778e-3f + rx2 * 7.93650794e-4f));
    float lx  = __logf(x);
    return fmaf(x - 0.5f, lx, -x) + HALF_L2PI + ser - __logf(prod);
}

// ---------------------------------------------------------------------------
// Kernel 1 (fused prep):
//   blocks [0, MMAXT)        : lgamma tables + constants (m = blockIdx.x)
//   blocks [MMAXT, MMAXT+BN) : list build, ONE BLOCK PER BATCH ROW,
//                              8 warps x 128-t slices, count->prefix->place.
// ---------------------------------------------------------------------------
__global__ void __launch_bounds__(256)
k_prep(const float* __restrict__ loc,
       const float* __restrict__ log_mean_conc,
       const float* __restrict__ log_conc,
       const float* __restrict__ log_scale,
       const float* __restrict__ sparse_prior_logit,
       const int*   __restrict__ z,
       float* __restrict__ out)
{
    if (blockIdx.x < MMAXT) {
        const int m = blockIdx.x;
        const int d = threadIdx.x;
        float kappa0 = expf(fminf(log_mean_conc[d], 12.0f));
        float a      = expf(log_conc[d]);
        float b      = expf(log_scale[d]);
        float a0     = 2.0f * a + 4.0f;                 // nu+1, nu = 2a+3
        float b0     = a0 * expf(sparse_prior_logit[d]);
        float l      = loc[d];
        float kl2    = LOG2EF * kappa0 * l;
        float cb     = (LOG2EF * LOG2EF) * fmaf(kappa0 * l, l, 2.0f * b);

        float lgA0 = fast_lgamma(a0);
        float lgB0 = fast_lgamma(b0);
        float lgAB = fast_lgamma(a0 + b0);
        float lgA  = fast_lgamma(a);
        float lgK  = fast_lgamma(kappa0);

        if (m == 0) {
            g_c4[d] = make_float4(kappa0, a, kl2, cb);
            g_a0[d]     = a0;
            g_b0[d]     = b0;
            g_lgA0[d]   = lgammaf(a0);
            g_lgB0[d]   = lgammaf(b0);
            g_lgA0B0[d] = lgammaf(a0 + b0);
            g_lgA[d]    = lgammaf(a);
            g_lgK[d]    = lgammaf(kappa0);
            if (d < BN) out[d] = 0.0f;                  // out is poisoned
        }

        float fm = (float)m;
        // telescoped Student-t constant, CLOSED FORM (Abel summation):
        // S(m) = Sum_{i=0}^{m-2}(a+(i+1)/2)[L(i+2)-L(i)], L(j)=log2(k0+j)
        //      = -log2[G(k0+m-1)/G(k0+2)]
        //        + (a+(m-2)/2)L(m-1) + (a+(m-1)/2)L(m)
        //        - (a+1/2)L(0) - (a+1)L(1)              (m >= 3)
        float tc = 0.0f;
        if (m >= 1) {
            float t10 = fmaf(cb, kappa0, -kl2 * kl2);   // t1 at M=0 (scaled)
            float p0  = t10 * (kappa0 + 1.0f);
            tc = a * __log2f(p0);
            if (m == 2) {
                tc += (a + 0.5f) * (__log2f(kappa0 + 2.0f) - __log2f(kappa0));
            } else if (m >= 3) {
                float mid = LOG2EF * (fast_lgamma(kappa0 + fm - 1.0f)
                                    - fast_lgamma(kappa0 + 2.0f));
                tc += -mid
                    + fmaf(0.5f, fm - 2.0f, a) * __log2f(kappa0 + fm - 1.0f)
                    + fmaf(0.5f, fm - 1.0f, a) * __log2f(kappa0 + fm)
                    - (a + 0.5f) * __log2f(kappa0)            // c_0 = a+1/2
                    - (a + 1.0f) * __log2f(kappa0 + 1.0f);    // c_1 = a+1
            }
        }
        g_tabNZ[m * DN + d] = (fast_lgamma(a0 + fm)           - lgA0)
                            + (fast_lgamma(fmaf(0.5f, fm, a)) - lgA)
                            + (fast_lgamma(kappa0 + fm)       - lgK)
                            + LN2F * tc;
        g_tabB0[m * DN + d] = fast_lgamma(b0 + fm)            - lgB0;
        g_tabAB[m * DN + d] = fast_lgamma(a0 + b0 + fm)       - lgAB;
    } else {
        // ---- list build: one BLOCK per batch row, 8 warps x 128-t slices ----
        __shared__ int cntw[8][KMAX];    // per-slice counts
        __shared__ int basew[8][KMAX];   // per-slice start offsets (running)
        const int b    = blockIdx.x - MMAXT;
        const int wl   = threadIdx.x >> 5;
        const int lane = threadIdx.x & 31;
        const unsigned lmlt = (1u << lane) - 1u;
        const int* zr = z + b * TN;

        for (int i = threadIdx.x; i < 8 * KMAX; i += 256)
            ((int*)cntw)[i] = 0;
        __syncthreads();

        // Phase 1: count occurrences per cluster in this warp's 128-t slice
        const int tbase = wl * 128;
#pragma unroll
        for (int c = 0; c < 4; c++) {
            int t  = tbase + c * 32 + lane;
            int zv = __ldg(zr + t);
            unsigned mask = __match_any_sync(0xffffffffu, zv);
            if ((mask & lmlt) == 0)                       // group leader
                atomicAdd(&cntw[wl][zv], __popc(mask));
        }
        __syncthreads();

        // Phase 2: exclusive prefix over the 8 slices per cluster + totals
        if (threadIdx.x < KMAX) {
            int k = threadIdx.x;
            int run = 0;
#pragma unroll
            for (int w = 0; w < 8; w++) {
                basew[w][k] = run;
                run += cntw[w][k];
            }
            g_cnt[b * KMAX + k] = run;
        }
        __syncthreads();

        // Phase 3: place (stable): warp walks its slice in order, advancing
        // basew[wl][k] per sub-chunk (same proven match/rank scheme).
        int* bw = basew[wl];
#pragma unroll
        for (int c = 0; c < 4; c++) {
            int t  = tbase + c * 32 + lane;
            int zv = __ldg(zr + t);
            unsigned mask = __match_any_sync(0xffffffffu, zv);
            int rank = __popc(mask & lmlt);
            int base = bw[zv];
            __syncwarp();
            g_list[((size_t)(b * KMAX + zv)) * TN + base + rank] = t * (DN / 4);
            if (rank == 0)
                bw[zv] = base + __popc(mask);
            __syncwarp();
        }
        __syncthreads();   // makes this block's g_list writes visible block-wide

        // Phase 4: pad each list with 4 duplicates of the last entry
        if (threadIdx.x < KMAX) {
            int k = threadIdx.x;
            int c = g_cnt[b * KMAX + k];
            if (c > 0) {
                size_t base = ((size_t)(b * KMAX + k)) * TN;
                int last = g_list[base + c - 1];
#pragma unroll
                for (int i = 0; i < 4; i++) {
                    int idx = c + i;
                    if (idx > TN - 1) idx = TN - 1;
                    g_list[base + idx] = last;
                }
            }
        }
    }
}

// ---------------------------------------------------------------------------
// Sufficient-stat-only per-element update (the whole Student-t log sum is
// telescoped out of the loop). A padded/zero element is a no-op.
// ---------------------------------------------------------------------------
__device__ __forceinline__ void obs_lite(float x, float& w, float& s2p, float& m1)
{
    float nzf = (x > EPSF) ? 1.0f : 0.0f;
    float y   = __log2f(fmaxf(x, EPSF));
    float yn  = y * nzf;
    w   += yn;
    s2p  = fmaf(yn, y, s2p);
    m1  += nzf;
}

// ---------------------------------------------------------------------------
// Chain-end terms for one dim. Loads its own per-dim constants (keeps the
// main-loop register set small). Telescoped Student-t final term:
//   -(a + M/2) * ln Q_final, Q_final = (s2p*kn - w^2)(kn - 1), kn = k0 + M
// ---------------------------------------------------------------------------
__device__ __forceinline__ float tail3(int d, int cnt, float m1, float w, float s2p)
{
    const float4 C = __ldg(&g_c4[d]);            // {kappa0, a, kl2, cb}
    const float kap = C.x, a = C.y, kl2 = C.z;
    const int M1 = (int)m1;
    const int Z  = cnt - M1;
    float s1  = w - kl2;
    float kn  = kap + m1;
    float t1f = fmaf(s2p, kn, -w * w);
    float qf  = t1f * (kn - 1.0f);
    float lq  = __log2f(fmaxf(qf, 1e-37f));
    float cf  = (m1 > 0.5f) ? fmaf(0.5f, m1, a) : 0.0f;   // gate M=0
    float r = fmaf(C1F, m1, -LN2F * s1);     // -0.5*ln(pi) residue, -Sum y
    r -= LN2F * cf * lq;                     // -(a+M/2)*ln(Q_final)
    if (cnt < MMAXT) {
        r += g_tabNZ[M1 * DN + d]
           + g_tabB0[Z  * DN + d]
           - g_tabAB[cnt * DN + d];
    } else {
        // rare fallback: direct evaluation (exact small loop)
        float a0 = g_a0[d], b0 = g_b0[d];
        float tc = 0.0f;
        if (M1 >= 1) {
            float t10 = fmaf(C.w, kap, -kl2 * kl2);
            float p0  = t10 * (kap + 1.0f);
            tc = a * __log2f(p0);
            for (int i = 0; i + 2 <= M1; i++) {
                float ratio = __fdividef(kap + (float)(i + 2), kap + (float)i);
                tc = fmaf(fmaf(0.5f, (float)(i + 1), a), __log2f(ratio), tc);
            }
        }
        r += LN2F * tc
           + (lgammaf(a0 + m1)              - g_lgA0[d])
           + (lgammaf(b0 + (float)Z)        - g_lgB0[d])
           + (lgammaf(fmaf(0.5f, m1, a))    - g_lgA[d])
           + (lgammaf(kap + m1)             - g_lgK[d])
           - (lgammaf(a0 + b0 + (float)cnt) - g_lgA0B0[d]);
    }
    return r;
}

// ---------------------------------------------------------------------------
// Kernel 2: main chain evaluation.
// One CTA per (b,k) chain, 64 threads; thread t owns dims 4t..4t+3. Minimal
// loop-live register set: only {w,s2p,m}x4 + depth-2 float4 pipeline; per-dim
// constants are re-loaded in the tail. Lists padded -> no index clamps.
// ---------------------------------------------------------------------------
__global__ void __launch_bounds__(64)
k_main(const float* __restrict__ X, float* __restrict__ out)
{
    const int id = blockIdx.x;            // chain id = b*KMAX + k
    const int b  = id >> 7;
    const int k  = id & (KMAX - 1);
    const int t  = threadIdx.x;           // dims 4t..4t+3

    const int cnt = g_cnt[id];
    float accN = 0.0f;

    if (cnt > 0) {
        // seed stats from constants (scalar loads; float4s not kept live)
        const float* cS = (const float*)g_c4;     // [d].{x,y,z,w} flattened
        float w0 = __ldg(cS + (4 * t + 0) * 4 + 2), p0 = __ldg(cS + (4 * t + 0) * 4 + 3), m0 = 0.f;
        float w1 = __ldg(cS + (4 * t + 1) * 4 + 2), p1 = __ldg(cS + (4 * t + 1) * 4 + 3), m1 = 0.f;
        float w2 = __ldg(cS + (4 * t + 2) * 4 + 2), p2 = __ldg(cS + (4 * t + 2) * 4 + 3), m2 = 0.f;
        float w3 = __ldg(cS + (4 * t + 3) * 4 + 2), p3 = __ldg(cS + (4 * t + 3) * 4 + 3), m3 = 0.f;

        const int* lst = g_list + (size_t)id * TN;
        const float4* Xb = (const float4*)X + ((size_t)b * TN) * (DN / 4) + t;

        // prime depth-2 pipeline (padded list: no clamps needed)
        int oa = __ldg(lst);
        int ob = __ldg(lst + 1);
        float4 x0 = __ldg(Xb + (size_t)oa);
        float4 x1 = __ldg(Xb + (size_t)ob);

        const int cnt2 = (cnt + 1) & ~1;           // round up to even
        for (int j = 0; j < cnt2; j += 2) {
            int on0 = __ldg(lst + j + 2);
            int on1 = __ldg(lst + j + 3);
            float4 xn0 = __ldg(Xb + (size_t)on0);
            float4 xn1 = __ldg(Xb + (size_t)on1);

            // slot 0 (always in range: j < cnt)
            obs_lite(x0.x, w0, p0, m0);
            obs_lite(x0.y, w1, p1, m1);
            obs_lite(x0.z, w2, p2, m2);
            obs_lite(x0.w, w3, p3, m3);

            // slot 1 (mask padded element to 0 -> no-op)
            float msk = (j + 1 < cnt) ? 1.0f : 0.0f;
            obs_lite(x1.x * msk, w0, p0, m0);
            obs_lite(x1.y * msk, w1, p1, m1);
            obs_lite(x1.z * msk, w2, p2, m2);
            obs_lite(x1.w * msk, w3, p3, m3);

            x0 = xn0;
            x1 = xn1;
        }

        const int d0 = 4 * t;
        accN  = tail3(d0,     cnt, m0, w0, p0);
        accN += tail3(d0 + 1, cnt, m1, w1, p1);
        accN += tail3(d0 + 2, cnt, m2, w2, p2);
        accN += tail3(d0 + 3, cnt, m3, w3, p3);
    }

    // CRP (fully telescoped): Sum_k lgamma(cnt_k) - lgamma(T+1) per batch row
    if (t == 0) {
        if (cnt > 0) accN += fast_lgamma((float)cnt);
        if (k == 0)  accN -= lgammaf((float)(TN + 1));
    }

    // 2-warp reduction
    const int lane = t & 31, wid = t >> 5;
#pragma unroll
    for (int o = 16; o; o >>= 1)
        accN += __shfl_down_sync(0xffffffffu, accN, o);
    __shared__ float wsum[2];
    if (lane == 0) wsum[wid] = accN;
    __syncthreads();
    if (t == 0)
        atomicAdd(&out[b], -(wsum[0] + wsum[1]));
}

// ---------------------------------------------------------------------------
// Entry point. Inputs: X, loc, log_mean_conc, log_conc, log_scale,
// sparse_prior_logit, z. Output: float[BN].
// ---------------------------------------------------------------------------
extern "C" void kernel_launch(void* const* d_in, const int* in_sizes, int n_in,
                              void* d_out, int out_size)
{
    const float* X   = (const float*)d_in[0];
    const float* loc = (const float*)d_in[1];
    const float* lmc = (const float*)d_in[2];
    const float* lc  = (const float*)d_in[3];
    const float* ls  = (const float*)d_in[4];
    const float* spl = (const float*)d_in[5];
    const int*   z   = (const int*)d_in[6];
    float* out = (float*)d_out;

    k_prep<<<MMAXT + BN, 256>>>(loc, lmc, lc, ls, spl, z, out);
    k_main<<<BN * KMAX, 64>>>(X, out);
}

// round 16
// speedup vs baseline: 1.3026x; 1.1603x over previous
#include <cuda_runtime.h>
#include <cstdint>

// Problem constants (match reference)
#define BN 64
#define TN 1024
#define DN 256
#define KMAX 128
#define EPSF 1e-3f
#define MMAXT 64                        // table depth (max cluster size covered)
#define HALF_L2PI 0.91893853320467274f  // 0.5*log(2*pi)
#define LN2F 0.69314718055994531f
#define LOG2EF 1.44269504088896340f
// C1 = ln(log2e) - 0.5*ln(pi)  (per-nonzero-obs scale residue)
#define C1F (-0.20585202294f)

// ---------------------------------------------------------------------------
// Static device scratch
// ---------------------------------------------------------------------------
__device__ int   g_cnt [BN * KMAX];
__device__ int   g_list[BN * KMAX * TN];   // PRE-SCALED float4-row offsets, padded +4

// per-dim packed loop constants: {kappa0, a, kl2, cb}
__device__ float4 g_c4[DN];
// fallback-path constants
__device__ float g_a0[DN], g_b0[DN];
__device__ float g_lgA0B0[DN], g_lgA0[DN], g_lgB0[DN], g_lgA[DN], g_lgK[DN];

// tables indexed by count m (telescoped chain-end sums)
__device__ float g_tabNZ[MMAXT * DN];
__device__ float g_tabB0[MMAXT * DN];   // lg(b0+m)-lg(b0)
__device__ float g_tabAB[MMAXT * DN];   // lg(a0+b0+m)-lg(a0+b0)

// ---------------------------------------------------------------------------
// Fast lgamma for x > 0: shift to x>=8 (unrolled, predicated), then Stirling.
// ---------------------------------------------------------------------------
__device__ __forceinline__ float fast_lgamma(float x)
{
    float prod = 1.0f;
#pragma unroll
    for (int i = 0; i < 8; i++) {
        if (x < 8.0f) { prod *= x; x += 1.0f; }
    }
    float rx  = __frcp_rn(x);
    float rx2 = rx * rx;
    float ser = rx * (8.33333333e-2f + rx2 * (-2.77777778e-3f + rx2 * 7.93650794e-4f));
    float lx  = __logf(x);
    return fmaf(x - 0.5f, lx, -x) + HALF_L2PI + ser - __logf(prod);
}

// ---------------------------------------------------------------------------
// Kernel 1 (fused prep):
//   blocks [0, MMAXT)        : lgamma tables + constants (m = blockIdx.x)
//   blocks [MMAXT, MMAXT+BN) : list build, ONE BLOCK PER BATCH ROW,
//                              8 warps x 128-t slices, count->prefix->place.
// ---------------------------------------------------------------------------
__global__ void __launch_bounds__(256)
k_prep(const float* __restrict__ loc,
       const float* __restrict__ log_mean_conc,
       const float* __restrict__ log_conc,
       const float* __restrict__ log_scale,
       const float* __restrict__ sparse_prior_logit,
       const int*   __restrict__ z,
       float* __restrict__ out)
{
    if (blockIdx.x < MMAXT) {
        const int m = blockIdx.x;
        const int d = threadIdx.x;
        float kappa0 = expf(fminf(log_mean_conc[d], 12.0f));
        float a      = expf(log_conc[d]);
        float b      = expf(log_scale[d]);
        float a0     = 2.0f * a + 4.0f;                 // nu+1, nu = 2a+3
        float b0     = a0 * expf(sparse_prior_logit[d]);
        float l      = loc[d];
        float kl2    = LOG2EF * kappa0 * l;
        float cb     = (LOG2EF * LOG2EF) * fmaf(kappa0 * l, l, 2.0f * b);

        float lgA0 = fast_lgamma(a0);
        float lgB0 = fast_lgamma(b0);
        float lgAB = fast_lgamma(a0 + b0);
        float lgA  = fast_lgamma(a);
        float lgK  = fast_lgamma(kappa0);

        if (m == 0) {
            g_c4[d] = make_float4(kappa0, a, kl2, cb);
            g_a0[d]     = a0;
            g_b0[d]     = b0;
            g_lgA0[d]   = lgammaf(a0);
            g_lgB0[d]   = lgammaf(b0);
            g_lgA0B0[d] = lgammaf(a0 + b0);
            g_lgA[d]    = lgammaf(a);
            g_lgK[d]    = lgammaf(kappa0);
            if (d < BN) out[d] = 0.0f;                  // out is poisoned
        }

        float fm = (float)m;
        // telescoped Student-t constant, CLOSED FORM (Abel summation):
        // S(m) = Sum_{i=0}^{m-2}(a+(i+1)/2)[L(i+2)-L(i)], L(j)=log2(k0+j)
        //      = -log2[G(k0+m-1)/G(k0+2)]
        //        + (a+(m-2)/2)L(m-1) + (a+(m-1)/2)L(m)
        //        - (a+1/2)L(0) - (a+1)L(1)              (m >= 3)
        float tc = 0.0f;
        if (m >= 1) {
            float t10 = fmaf(cb, kappa0, -kl2 * kl2);   // t1 at M=0 (scaled)
            float p0  = t10 * (kappa0 + 1.0f);
            tc = a * __log2f(p0);
            if (m == 2) {
                tc += (a + 0.5f) * (__log2f(kappa0 + 2.0f) - __log2f(kappa0));
            } else if (m >= 3) {
                float mid = LOG2EF * (fast_lgamma(kappa0 + fm - 1.0f)
                                    - fast_lgamma(kappa0 + 2.0f));
                tc += -mid
                    + fmaf(0.5f, fm - 2.0f, a) * __log2f(kappa0 + fm - 1.0f)
                    + fmaf(0.5f, fm - 1.0f, a) * __log2f(kappa0 + fm)
                    - (a + 0.5f) * __log2f(kappa0)            // c_0 = a+1/2
                    - (a + 1.0f) * __log2f(kappa0 + 1.0f);    // c_1 = a+1
            }
        }
        g_tabNZ[m * DN + d] = (fast_lgamma(a0 + fm)           - lgA0)
                            + (fast_lgamma(fmaf(0.5f, fm, a)) - lgA)
                            + (fast_lgamma(kappa0 + fm)       - lgK)
                            + LN2F * tc;
        g_tabB0[m * DN + d] = fast_lgamma(b0 + fm)            - lgB0;
        g_tabAB[m * DN + d] = fast_lgamma(a0 + b0 + fm)       - lgAB;
    } else {
        // ---- list build: one BLOCK per batch row, 8 warps x 128-t slices ----
        __shared__ int cntw[8][KMAX];    // per-slice counts
        __shared__ int basew[8][KMAX];   // per-slice start offsets (running)
        const int b    = blockIdx.x - MMAXT;
        const int wl   = threadIdx.x >> 5;
        const int lane = threadIdx.x & 31;
        const unsigned lmlt = (1u << lane) - 1u;
        const int* zr = z + b * TN;

        for (int i = threadIdx.x; i < 8 * KMAX; i += 256)
            ((int*)cntw)[i] = 0;
        __syncthreads();

        // Phase 1: count occurrences per cluster in this warp's 128-t slice
        const int tbase = wl * 128;
#pragma unroll
        for (int c = 0; c < 4; c++) {
            int t  = tbase + c * 32 + lane;
            int zv = __ldg(zr + t);
            unsigned mask = __match_any_sync(0xffffffffu, zv);
            if ((mask & lmlt) == 0)                       // group leader
                atomicAdd(&cntw[wl][zv], __popc(mask));
        }
        __syncthreads();

        // Phase 2: exclusive prefix over the 8 slices per cluster + totals
        if (threadIdx.x < KMAX) {
            int k = threadIdx.x;
            int run = 0;
#pragma unroll
            for (int w = 0; w < 8; w++) {
                basew[w][k] = run;
                run += cntw[w][k];
            }
            g_cnt[b * KMAX + k] = run;
        }
        __syncthreads();

        // Phase 3: place (stable): warp walks its slice in order, advancing
        // basew[wl][k] per sub-chunk (same proven match/rank scheme).
        int* bw = basew[wl];
#pragma unroll
        for (int c = 0; c < 4; c++) {
            int t  = tbase + c * 32 + lane;
            int zv = __ldg(zr + t);
            unsigned mask = __match_any_sync(0xffffffffu, zv);
            int rank = __popc(mask & lmlt);
            int base = bw[zv];
            __syncwarp();
            g_list[((size_t)(b * KMAX + zv)) * TN + base + rank] = t * (DN / 4);
            if (rank == 0)
                bw[zv] = base + __popc(mask);
            __syncwarp();
        }
        __syncthreads();   // makes this block's g_list writes visible block-wide

        // Phase 4: pad each list with 4 duplicates of the last entry
        if (threadIdx.x < KMAX) {
            int k = threadIdx.x;
            int c = g_cnt[b * KMAX + k];
            if (c > 0) {
                size_t base = ((size_t)(b * KMAX + k)) * TN;
                int last = g_list[base + c - 1];
#pragma unroll
                for (int i = 0; i < 4; i++) {
                    int idx = c + i;
                    if (idx > TN - 1) idx = TN - 1;
                    g_list[base + idx] = last;
                }
            }
        }
    }
}

// ---------------------------------------------------------------------------
// Sufficient-stat-only per-element update (the whole Student-t log sum is
// telescoped out of the loop). A padded/zero element is a no-op.
// ---------------------------------------------------------------------------
__device__ __forceinline__ void obs_lite(float x, float& w, float& s2p, float& m1)
{
    float nzf = (x > EPSF) ? 1.0f : 0.0f;
    float y   = __log2f(fmaxf(x, EPSF));
    float yn  = y * nzf;
    w   += yn;
    s2p  = fmaf(yn, y, s2p);
    m1  += nzf;
}

// ---------------------------------------------------------------------------
// Chain-end terms for one dim (constants passed in registers — measured
// faster than re-loading them here). Telescoped Student-t final term:
//   -(a + M/2) * ln Q_final, Q_final = (s2p*kn - w^2)(kn - 1), kn = k0 + M
// ---------------------------------------------------------------------------
__device__ __forceinline__ float tail3(int d, int cnt, float m1, float w, float s2p,
                                       float kap, float a, float kl2, float cbv)
{
    const int M1 = (int)m1;
    const int Z  = cnt - M1;
    float s1  = w - kl2;
    float kn  = kap + m1;
    float t1f = fmaf(s2p, kn, -w * w);
    float qf  = t1f * (kn - 1.0f);
    float lq  = __log2f(fmaxf(qf, 1e-37f));
    float cf  = (m1 > 0.5f) ? fmaf(0.5f, m1, a) : 0.0f;   // gate M=0
    float r = fmaf(C1F, m1, -LN2F * s1);     // -0.5*ln(pi) residue, -Sum y
    r -= LN2F * cf * lq;                     // -(a+M/2)*ln(Q_final)
    if (cnt < MMAXT) {
        r += g_tabNZ[M1 * DN + d]
           + g_tabB0[Z  * DN + d]
           - g_tabAB[cnt * DN + d];
    } else {
        // rare fallback: direct evaluation (exact small loop)
        float a0 = g_a0[d], b0 = g_b0[d];
        float tc = 0.0f;
        if (M1 >= 1) {
            float t10 = fmaf(cbv, kap, -kl2 * kl2);
            float p0  = t10 * (kap + 1.0f);
            tc = a * __log2f(p0);
            for (int i = 0; i + 2 <= M1; i++) {
                float ratio = __fdividef(kap + (float)(i + 2), kap + (float)i);
                tc = fmaf(fmaf(0.5f, (float)(i + 1), a), __log2f(ratio), tc);
            }
        }
        r += LN2F * tc
           + (lgammaf(a0 + m1)              - g_lgA0[d])
           + (lgammaf(b0 + (float)Z)        - g_lgB0[d])
           + (lgammaf(fmaf(0.5f, m1, a))    - g_lgA[d])
           + (lgammaf(kap + m1)             - g_lgK[d])
           - (lgammaf(a0 + b0 + (float)cnt) - g_lgA0B0[d]);
    }
    return r;
}

// ---------------------------------------------------------------------------
// Kernel 2: main chain evaluation (R14 config — measured best: 24.9us).
// One CTA per (b,k) chain, 64 threads; thread t owns dims 4t..4t+3. The CTA
// streams its cluster's X rows as coalesced float4, 2 time-steps per loop
// with depth-2 prefetch. Lists padded -> no index clamps; padded slots are
// masked to x=0 (no-op through obs_lite).
// ---------------------------------------------------------------------------
__global__ void __launch_bounds__(64)
k_main(const float* __restrict__ X, float* __restrict__ out)
{
    const int id = blockIdx.x;            // chain id = b*KMAX + k
    const int b  = id >> 7;
    const int k  = id & (KMAX - 1);
    const int t  = threadIdx.x;           // dims 4t..4t+3

    const int cnt = g_cnt[id];
    float accN = 0.0f;

    if (cnt > 0) {
        const float4 C0 = __ldg(&g_c4[4 * t]);      // {kappa0, a, kl2, cb}
        const float4 C1 = __ldg(&g_c4[4 * t + 1]);
        const float4 C2 = __ldg(&g_c4[4 * t + 2]);
        const float4 C3 = __ldg(&g_c4[4 * t + 3]);

        const int* lst = g_list + (size_t)id * TN;
        const float4* Xb = (const float4*)X + ((size_t)b * TN) * (DN / 4) + t;

        float w0 = C0.z, p0 = C0.w, m0 = 0.f;
        float w1 = C1.z, p1 = C1.w, m1 = 0.f;
        float w2 = C2.z, p2 = C2.w, m2 = 0.f;
        float w3 = C3.z, p3 = C3.w, m3 = 0.f;

        // prime depth-2 pipeline (padded list: no clamps needed)
        int oa = __ldg(lst);
        int ob = __ldg(lst + 1);
        float4 x0 = __ldg(Xb + (size_t)oa);
        float4 x1 = __ldg(Xb + (size_t)ob);

        const int cnt2 = (cnt + 1) & ~1;           // round up to even
        for (int j = 0; j < cnt2; j += 2) {
            int on0 = __ldg(lst + j + 2);
            int on1 = __ldg(lst + j + 3);
            float4 xn0 = __ldg(Xb + (size_t)on0);
            float4 xn1 = __ldg(Xb + (size_t)on1);

            // slot 0 (always in range: j < cnt)
            obs_lite(x0.x, w0, p0, m0);
            obs_lite(x0.y, w1, p1, m1);
            obs_lite(x0.z, w2, p2, m2);
            obs_lite(x0.w, w3, p3, m3);

            // slot 1 (mask padded element to 0 -> no-op)
            float msk = (j + 1 < cnt) ? 1.0f : 0.0f;
            obs_lite(x1.x * msk, w0, p0, m0);
            obs_lite(x1.y * msk, w1, p1, m1);
            obs_lite(x1.z * msk, w2, p2, m2);
            obs_lite(x1.w * msk, w3, p3, m3);

            x0 = xn0;
            x1 = xn1;
        }

        const int d0 = 4 * t;
        accN  = tail3(d0,     cnt, m0, w0, p0, C0.x, C0.y, C0.z, C0.w);
        accN += tail3(d0 + 1, cnt, m1, w1, p1, C1.x, C1.y, C1.z, C1.w);
        accN += tail3(d0 + 2, cnt, m2, w2, p2, C2.x, C2.y, C2.z, C2.w);
        accN += tail3(d0 + 3, cnt, m3, w3, p3, C3.x, C3.y, C3.z, C3.w);
    }

    // CRP (fully telescoped): Sum_k lgamma(cnt_k) - lgamma(T+1) per batch row
    if (t == 0) {
        if (cnt > 0) accN += fast_lgamma((float)cnt);
        if (k == 0)  accN -= lgammaf((float)(TN + 1));
    }

    // 2-warp reduction
    const int lane = t & 31, wid = t >> 5;
#pragma unroll
    for (int o = 16; o; o >>= 1)
        accN += __shfl_down_sync(0xffffffffu, accN, o);
    __shared__ float wsum[2];
    if (lane == 0) wsum[wid] = accN;
    __syncthreads();
    if (t == 0)
        atomicAdd(&out[b], -(wsum[0] + wsum[1]));
}

// ---------------------------------------------------------------------------
// Entry point. Inputs: X, loc, log_mean_conc, log_conc, log_scale,
// sparse_prior_logit, z. Output: float[BN].
// ---------------------------------------------------------------------------
extern "C" void kernel_launch(void* const* d_in, const int* in_sizes, int n_in,
                              void* d_out, int out_size)
{
    const float* X   = (const float*)d_in[0];
    const float* loc = (const float*)d_in[1];
    const float* lmc = (const float*)d_in[2];
    const float* lc  = (const float*)d_in[3];
    const float* ls  = (const float*)d_in[4];
    const float* spl = (const float*)d_in[5];
    const int*   z   = (const int*)d_in[6];
    float* out = (float*)d_out;

    k_prep<<<MMAXT + BN, 256>>>(loc, lmc, lc, ls, spl, z, out);
    k_main<<<BN * KMAX, 64>>>(X, out);
}